// round 8
// baseline (speedup 1.0000x reference)
#include <cuda_runtime.h>
#include <cuda_bf16.h>
#include <math.h>
#include <stdint.h>

// ---------------------------------------------------------------------------
// Swin block: B=32, H=W=56, D=192, HEADS=6, DH=32, WS=7, SHIFT=3, no pad,
// no attention mask (per reference).
// R8: LN1 fused into attn_fused prologue (a1 buffer + ln1 kernel deleted);
// A-tile is a static SMEM tile written by the in-kernel LN, only B (weights)
// streams through cp.async.
// ---------------------------------------------------------------------------

#define NHW   3136
#define NTOK  100352
#define DIM   192
#define NWIN  2048

__device__ __nv_bfloat16 g_ao [(size_t)NTOK * DIM];   // attn out (window order)
__device__ float         g_x2 [(size_t)NTOK * DIM];   // x2 fp32 (plain order)
__device__ __nv_bfloat16 g_x2b[(size_t)NTOK * DIM];   // x2 bf16 (plain order)
__device__ __nv_bfloat16 g_hid[(size_t)NTOK * 384];   // fc1 GELU out
__device__ __nv_bfloat16 g_wqkv[576 * 192];
__device__ __nv_bfloat16 g_wout[192 * 192];
__device__ __nv_bfloat16 g_w1  [384 * 192];           // gamma2-folded
__device__ __nv_bfloat16 g_w2  [192 * 384];
__device__ float2        g_st1 [384];                 // (S_n, T_n) for fc1 affine
__device__ float2        g_pbuf[6 * NTOK];            // per-slot (sum, sumsq)
__device__ float2        g_mstat[NTOK];               // (mean, rstd) of x2

__device__ __forceinline__ int src_index(int r) {
    int w = r / 49, p = r % 49;
    int b  = w >> 6;
    int wy = (w & 63) >> 3;
    int wx = w & 7;
    int py = p / 7, px = p % 7;
    int h2 = wy * 7 + py;
    int w2 = wx * 7 + px;
    int hs = h2 + 3; if (hs >= 56) hs -= 56;
    int ws = w2 + 3; if (ws >= 56) ws -= 56;
    return b * NHW + hs * 56 + ws;
}

// ---------------------------------------------------------------------------
// PTX helpers (sm_80+; safe on plain sm_100 ptxas target)
// ---------------------------------------------------------------------------
__device__ __forceinline__ uint32_t smem_u32(const void* p) {
    uint32_t a;
    asm("{ .reg .u64 t; cvta.to.shared.u64 t, %1; cvt.u32.u64 %0, t; }" : "=r"(a) : "l"(p));
    return a;
}
__device__ __forceinline__ void cp_async16(uint32_t dst, const void* src) {
    asm volatile("cp.async.ca.shared.global [%0], [%1], 16;" :: "r"(dst), "l"(src));
}
#define CP_COMMIT()  asm volatile("cp.async.commit_group;" ::: "memory")
#define CP_WAIT(n)   asm volatile("cp.async.wait_group %0;" :: "n"(n) : "memory")

__device__ __forceinline__ void ldsm4(uint32_t* r, uint32_t addr) {
    asm volatile("ldmatrix.sync.aligned.m8n8.x4.shared.b16 {%0,%1,%2,%3}, [%4];"
        : "=r"(r[0]), "=r"(r[1]), "=r"(r[2]), "=r"(r[3]) : "r"(addr));
}
__device__ __forceinline__ void ldsm2(uint32_t* r, uint32_t addr) {
    asm volatile("ldmatrix.sync.aligned.m8n8.x2.shared.b16 {%0,%1}, [%2];"
        : "=r"(r[0]), "=r"(r[1]) : "r"(addr));
}
__device__ __forceinline__ void ldsm4t(uint32_t* r, uint32_t addr) {
    asm volatile("ldmatrix.sync.aligned.m8n8.x4.trans.shared.b16 {%0,%1,%2,%3}, [%4];"
        : "=r"(r[0]), "=r"(r[1]), "=r"(r[2]), "=r"(r[3]) : "r"(addr));
}
__device__ __forceinline__ void mma_bf16(float* c, const uint32_t* a, const uint32_t* b) {
    asm volatile(
        "mma.sync.aligned.m16n8k16.row.col.f32.bf16.bf16.f32 "
        "{%0,%1,%2,%3}, {%4,%5,%6,%7}, {%8,%9}, {%0,%1,%2,%3};"
        : "+f"(c[0]), "+f"(c[1]), "+f"(c[2]), "+f"(c[3])
        : "r"(a[0]), "r"(a[1]), "r"(a[2]), "r"(a[3]), "r"(b[0]), "r"(b[1]));
}
__device__ __forceinline__ float gelu_exact(float v) {
    return 0.5f * v * (1.0f + erff(v * 0.7071067811865476f));
}
__device__ __forceinline__ uint32_t packbf(float a, float b) {
    __nv_bfloat162 t = __floats2bfloat162_rn(a, b);
    return *(uint32_t*)&t;
}

// ---------------------------------------------------------------------------
// Weight conversion fp32 -> bf16 (wqkv, wout, w2)
// ---------------------------------------------------------------------------
__global__ void wcvt(const float* __restrict__ wqkv, const float* __restrict__ wout,
                     const float* __restrict__ w2) {
    int i = blockIdx.x * 256 + threadIdx.x;
    if (i < 110592)       g_wqkv[i]          = __float2bfloat16(wqkv[i]);
    else if (i < 147456)  g_wout[i - 110592] = __float2bfloat16(wout[i - 110592]);
    else                  g_w2[i - 147456]   = __float2bfloat16(w2[i - 147456]);
}

// Fold ln2 gamma into w1; compute per-n (S, T). One warp per n.
__global__ void prep1(const float* __restrict__ w1, const float* __restrict__ g2,
                      const float* __restrict__ b2) {
    int n = blockIdx.x * 8 + (threadIdx.x >> 5);
    int lane = threadIdx.x & 31;
    float S = 0.0f, T = 0.0f;
#pragma unroll
    for (int j = 0; j < 6; j++) {
        int k = lane + 32 * j;
        float w = w1[n * 192 + k];
        __nv_bfloat16 wb = __float2bfloat16(w * g2[k]);
        g_w1[n * 192 + k] = wb;
        S += __bfloat162float(wb);
        T += b2[k] * w;
    }
#pragma unroll
    for (int o = 16; o; o >>= 1) {
        S += __shfl_xor_sync(0xffffffffu, S, o);
        T += __shfl_xor_sync(0xffffffffu, T, o);
    }
    if (lane == 0) g_st1[n] = make_float2(S, T);
}

// Final LN2 stats: reduce the 6 proj-epilogue partial slots per token.
__global__ void finstats() {
    int i = blockIdx.x * 256 + threadIdx.x;
    float s = 0.0f, q = 0.0f;
#pragma unroll
    for (int k = 0; k < 6; k++) {
        float2 p = g_pbuf[k * NTOK + i];
        s += p.x; q += p.y;
    }
    float mean = s * (1.0f / 192.0f);
    float var  = q * (1.0f / 192.0f) - mean * mean;
    g_mstat[i] = make_float2(mean, rsqrtf(var + 1e-5f));
}

// ---------------------------------------------------------------------------
// Fused LN1 + QKV-GEMM + window attention.
// CTA = (window pair p, head h). 256 thr, 8 warps.
// Prologue: LN1 over gathered x rows -> static bf16 A tile [128][200] in SMEM
//           (rows 98-127 zeroed).
// Phase 1:  qkv[128x96] = A @ Whead^T + b; A-frags from static tile, B via
//           4-stage cp.async. Result q|k|v kept in SMEM.
// Phase 2:  per window: S=QK^T, register softmax, O=PV; write ao.
// ---------------------------------------------------------------------------
#define FBK   16
#define FSTG  4
#define FAROW 24                          // B pipeline smem row stride (bf16)
#define FWSZ  (96 * FAROW * 2)            // 4608 B per B stage
#define XSTR  200                         // A tile row stride (bf16)
#define QSTR  104                         // qkv smem row stride (bf16)
#define OFF_AT (FSTG * FWSZ)              // 18432
#define OFF_QS (OFF_AT + 128 * XSTR * 2)  // 69632
#define FUSED_SMEM (OFF_QS + 128 * QSTR * 2)  // 96256 B

__global__ __launch_bounds__(256, 2)
void attn_fused(const float* __restrict__ x,
                const float* __restrict__ g1,
                const float* __restrict__ be1,
                const float* __restrict__ bqkv,
                __nv_bfloat16* __restrict__ ao) {
    extern __shared__ char smem[];
    const int tid  = threadIdx.x;
    const int warp = tid >> 5;
    const int lane = tid & 31;
    const int g    = lane >> 2;
    const int tin  = lane & 3;
    const int l15  = lane & 15;
    const int lhi  = lane >> 4;
    const int p    = blockIdx.x;          // window pair
    const int h    = blockIdx.y;          // head
    const int R0   = p * 98;

    const uint32_t sb = smem_u32(smem);

    // ---- B prefetch (weights for this head's q/k/v rows) ----
    const bool bld = tid < 192;
    int brow = bld ? (tid >> 1) : 0;
    int bchk = tid & 1;
    const int bseg = brow >> 5;
    const __nv_bfloat16* Wg = g_wqkv + (size_t)(bseg * 192 + h * 32 + (brow & 31)) * 192 + bchk * 8;
    const uint32_t wsb = sb + (brow * FAROW + bchk * 8) * 2;

#pragma unroll
    for (int s = 0; s < FSTG - 1; s++) {
        if (bld) cp_async16(wsb + s * FWSZ, Wg + s * FBK);
        CP_COMMIT();
    }

    // ---- LN1 prologue: gathered x rows -> static A tile (bf16) ----
    {
        __nv_bfloat16* At = (__nv_bfloat16*)(smem + OFF_AT);
        float gv[6], bv[6];
#pragma unroll
        for (int i = 0; i < 6; i++) {
            gv[i] = g1[lane + 32 * i];
            bv[i] = be1[lane + 32 * i];
        }
        const int r0w = warp * 16;
#pragma unroll 2
        for (int r = r0w; r < r0w + 16; r++) {
            if (r < 98) {
                const float* xr = x + (size_t)src_index(R0 + r) * DIM;
                float v[6];
#pragma unroll
                for (int i = 0; i < 6; i++) v[i] = xr[lane + 32 * i];
                float s = v[0] + v[1] + v[2] + v[3] + v[4] + v[5];
#pragma unroll
                for (int o = 16; o; o >>= 1) s += __shfl_xor_sync(0xffffffffu, s, o);
                float mean = s * (1.0f / 192.0f);
                float q = 0.0f;
#pragma unroll
                for (int i = 0; i < 6; i++) { float d = v[i] - mean; q += d * d; }
#pragma unroll
                for (int o = 16; o; o >>= 1) q += __shfl_xor_sync(0xffffffffu, q, o);
                float rstd = rsqrtf(q * (1.0f / 192.0f) + 1e-5f);
#pragma unroll
                for (int i = 0; i < 6; i++)
                    At[r * XSTR + lane + 32 * i] =
                        __float2bfloat16((v[i] - mean) * rstd * gv[i] + bv[i]);
            } else {
#pragma unroll
                for (int i = 0; i < 6; i++)
                    At[r * XSTR + lane + 32 * i] = __float2bfloat16(0.0f);
            }
        }
    }
    __syncthreads();

    // ---------------- Phase 1: QKV GEMM ----------------
    const int wm = (warp & 3) * 32;
    const int wn = (warp >> 2) * 48;

    float acc[2][6][4];
#pragma unroll
    for (int i = 0; i < 2; i++)
#pragma unroll
        for (int j = 0; j < 6; j++)
#pragma unroll
            for (int l = 0; l < 4; l++) acc[i][j][l] = 0.0f;

    // A-frag ldsm4 base in the static tile
    const uint32_t atbase = sb + OFF_AT + (uint32_t)(wm + l15) * (XSTR * 2) + lhi * 16;
    // B-frag ldsm4 base (pairs of n-frags)
    const uint32_t wbbase = sb
                          + (uint32_t)(wn + ((lane >> 4) & 1) * 8 + (lane & 7)) * (FAROW * 2)
                          + ((lane >> 3) & 1) * 16;

    for (int t = 0; t < 12; t++) {
        CP_WAIT(FSTG - 2);
        __syncthreads();
        const int tn = t + FSTG - 1;
        if (tn < 12) {
            const int s = tn % FSTG;
            if (bld) cp_async16(wsb + s * FWSZ, Wg + tn * FBK);
        }
        CP_COMMIT();

        const int st = t % FSTG;
        uint32_t af[2][4];
        ldsm4(af[0], atbase + t * 32);
        ldsm4(af[1], atbase + 16 * (XSTR * 2) + t * 32);

        uint32_t bq[3][4];
#pragma unroll
        for (int pr = 0; pr < 3; pr++)
            ldsm4(bq[pr], wbbase + st * FWSZ + pr * 16 * (FAROW * 2));

#pragma unroll
        for (int mt = 0; mt < 2; mt++)
#pragma unroll
            for (int pr = 0; pr < 3; pr++) {
                mma_bf16(acc[mt][2 * pr + 0], af[mt], &bq[pr][0]);
                mma_bf16(acc[mt][2 * pr + 1], af[mt], &bq[pr][2]);
            }
    }

    // epilogue: + bias, store q|k|v to SMEM (cols 0-31 q, 32-63 k, 64-95 v)
    __nv_bfloat16* qs = (__nv_bfloat16*)(smem + OFF_QS);
#pragma unroll
    for (int mt = 0; mt < 2; mt++) {
        const int r0 = wm + mt * 16 + g;
#pragma unroll
        for (int nt = 0; nt < 6; nt++) {
            const int nb  = wn + nt * 8;
            const int seg = nb >> 5;
            const int bcol = seg * 192 + h * 32 + (nb & 31) + 2 * tin;
            const float2 bv = *(const float2*)&bqkv[bcol];
            const int c = nb + 2 * tin;
            *(uint32_t*)&qs[r0 * QSTR + c]       = packbf(acc[mt][nt][0] + bv.x, acc[mt][nt][1] + bv.y);
            *(uint32_t*)&qs[(r0 + 8) * QSTR + c] = packbf(acc[mt][nt][2] + bv.x, acc[mt][nt][3] + bv.y);
        }
    }
    __syncthreads();

    // ---------------- Phase 2: attention ----------------
    const int wi = warp >> 2;             // window in pair
    const int mq = (warp & 3) * 16;       // row tile within window
    const int rb = wi * 49 + mq;
    const uint32_t qsu = sb + OFF_QS;

    float a7[7][4];
#pragma unroll
    for (int nt = 0; nt < 7; nt++)
#pragma unroll
        for (int c = 0; c < 4; c++) a7[nt][c] = 0.0f;

    const uint32_t kbase = qsu
        + (uint32_t)(wi * 49 + ((lane >> 4) & 1) * 8 + (lane & 7)) * (QSTR * 2)
        + 64 + ((lane >> 3) & 1) * 16;

#pragma unroll
    for (int kc = 0; kc < 2; kc++) {
        uint32_t qa[4];
        ldsm4(qa, qsu + (uint32_t)(rb + l15) * (QSTR * 2) + kc * 32 + lhi * 16);
        uint32_t kq[3][4];
#pragma unroll
        for (int pr = 0; pr < 3; pr++)
            ldsm4(kq[pr], kbase + kc * 32 + pr * 16 * (QSTR * 2));
        uint32_t k6[2];
        ldsm2(k6, qsu + (uint32_t)(wi * 49 + 48 + (lane & 7)) * (QSTR * 2)
                   + 64 + kc * 32 + ((lane >> 3) & 1) * 16);
#pragma unroll
        for (int pr = 0; pr < 3; pr++) {
            mma_bf16(a7[2 * pr + 0], qa, &kq[pr][0]);
            mma_bf16(a7[2 * pr + 1], qa, &kq[pr][2]);
        }
        mma_bf16(a7[6], qa, k6);
    }

    const float scale = 0.17677669529663687f;   // 1/sqrt(32)
    float mx0 = -1e30f, mx1 = -1e30f;
#pragma unroll
    for (int nt = 0; nt < 7; nt++) {
        int c0 = nt * 8 + 2 * tin;
        float* a = a7[nt];
        a[0] = (c0     < 49) ? a[0] * scale : -1e30f;
        a[1] = (c0 + 1 < 49) ? a[1] * scale : -1e30f;
        a[2] = (c0     < 49) ? a[2] * scale : -1e30f;
        a[3] = (c0 + 1 < 49) ? a[3] * scale : -1e30f;
        mx0 = fmaxf(mx0, fmaxf(a[0], a[1]));
        mx1 = fmaxf(mx1, fmaxf(a[2], a[3]));
    }
    mx0 = fmaxf(mx0, __shfl_xor_sync(0xffffffffu, mx0, 1));
    mx0 = fmaxf(mx0, __shfl_xor_sync(0xffffffffu, mx0, 2));
    mx1 = fmaxf(mx1, __shfl_xor_sync(0xffffffffu, mx1, 1));
    mx1 = fmaxf(mx1, __shfl_xor_sync(0xffffffffu, mx1, 2));

    float s0 = 0.0f, s1 = 0.0f;
    uint32_t pk[8][2];
#pragma unroll
    for (int nt = 0; nt < 7; nt++) {
        float* a = a7[nt];
        a[0] = __expf(a[0] - mx0);
        a[1] = __expf(a[1] - mx0);
        a[2] = __expf(a[2] - mx1);
        a[3] = __expf(a[3] - mx1);
        s0 += a[0] + a[1];
        s1 += a[2] + a[3];
        pk[nt][0] = packbf(a[0], a[1]);
        pk[nt][1] = packbf(a[2], a[3]);
    }
    pk[7][0] = 0u; pk[7][1] = 0u;
    s0 += __shfl_xor_sync(0xffffffffu, s0, 1);
    s0 += __shfl_xor_sync(0xffffffffu, s0, 2);
    s1 += __shfl_xor_sync(0xffffffffu, s1, 1);
    s1 += __shfl_xor_sync(0xffffffffu, s1, 2);

    float pv[4][4];
#pragma unroll
    for (int nt = 0; nt < 4; nt++)
#pragma unroll
        for (int c = 0; c < 4; c++) pv[nt][c] = 0.0f;

    const uint32_t vbase = qsu + (uint32_t)(wi * 49 + l15) * (QSTR * 2) + 128 + lhi * 16;

#pragma unroll
    for (int kc = 0; kc < 4; kc++) {
        uint32_t pa[4] = { pk[2 * kc][0], pk[2 * kc][1], pk[2 * kc + 1][0], pk[2 * kc + 1][1] };
        uint32_t vq[2][4];
#pragma unroll
        for (int pr = 0; pr < 2; pr++)
            ldsm4t(vq[pr], vbase + kc * 16 * (QSTR * 2) + pr * 32);
#pragma unroll
        for (int pr = 0; pr < 2; pr++) {
            mma_bf16(pv[2 * pr + 0], pa, &vq[pr][0]);
            mma_bf16(pv[2 * pr + 1], pa, &vq[pr][2]);
        }
    }

    const float inv0 = 1.0f / s0;
    const float inv1 = 1.0f / s1;
    const int rr0 = mq + g;
    if (rr0 < 49) {
        __nv_bfloat16* ob = ao + (size_t)(R0 + wi * 49 + rr0) * 192 + h * 32;
#pragma unroll
        for (int nt = 0; nt < 4; nt++)
            *(uint32_t*)&ob[nt * 8 + 2 * tin] = packbf(pv[nt][0] * inv0, pv[nt][1] * inv0);
    }
    if (rr0 + 8 < 49) {
        __nv_bfloat16* ob = ao + (size_t)(R0 + wi * 49 + rr0 + 8) * 192 + h * 32;
#pragma unroll
        for (int nt = 0; nt < 4; nt++)
            *(uint32_t*)&ob[nt * 8 + 2 * tin] = packbf(pv[nt][2] * inv1, pv[nt][3] * inv1);
    }
}

// ---------------------------------------------------------------------------
// bf16 GEMM (round-7 core). EPIs:
//   2: v += res[row]; fp32 store (fc2 -> out)
//   3: v += res[src(row)]; fp32 scatter store + bf16 copy + LN2 stat partials
//   4: LN2-affine (rstd*acc - mean*rstd*S + T + bias) then GELU, bf16 store
// ---------------------------------------------------------------------------
#define BM 128
#define BN 64
#define BK 16
#define STG 4
#define AROW 24

template <int EPI>
__global__ __launch_bounds__(256, 3)
void bgemm(const __nv_bfloat16* __restrict__ A, const __nv_bfloat16* __restrict__ W,
           const float* __restrict__ bias, void* __restrict__ outp,
           const float* __restrict__ res, int N, int K) {
    __shared__ __align__(16) __nv_bfloat16 As[STG][BM * AROW];
    __shared__ __align__(16) __nv_bfloat16 Ws[STG][BN * AROW];

    const int tid  = threadIdx.x;
    const int wid  = tid >> 5;
    const int lane = tid & 31;
    const int g    = lane >> 2;
    const int tin  = lane & 3;
    const int wm   = (wid & 3) * 32;
    const int wn   = (wid >> 2) * 32;
    const int row0 = blockIdx.y * BM;
    const int col0 = blockIdx.x * BN;

    const int arow = tid >> 1, achk = tid & 1;
    const int brow = (tid & 127) >> 1, bchk = tid & 1;
    const bool bld = tid < 128;

    const __nv_bfloat16* Ag = A + (size_t)(row0 + arow) * K + achk * 8;
    const __nv_bfloat16* Wg = W + (size_t)(col0 + brow) * K + bchk * 8;
    const uint32_t asb = smem_u32(As) + (arow * AROW + achk * 8) * 2;
    const uint32_t wsb = smem_u32(Ws) + (brow * AROW + bchk * 8) * 2;
    const uint32_t ASZ = BM * AROW * 2;
    const uint32_t WSZ = BN * AROW * 2;

    const int T = K / BK;
#pragma unroll
    for (int s = 0; s < STG - 1; s++) {
        cp_async16(asb + s * ASZ, Ag + s * BK);
        if (bld) cp_async16(wsb + s * WSZ, Wg + s * BK);
        CP_COMMIT();
    }

    float acc[2][4][4];
#pragma unroll
    for (int i = 0; i < 2; i++)
#pragma unroll
        for (int j = 0; j < 4; j++)
#pragma unroll
            for (int l = 0; l < 4; l++) acc[i][j][l] = 0.0f;

    const uint32_t albase = smem_u32(As) + ((wm + (lane & 15)) * AROW) * 2 + (lane >> 4) * 16;
    const uint32_t wbbase = smem_u32(Ws)
                          + (uint32_t)(wn + ((lane >> 4) & 1) * 8 + (lane & 7)) * (AROW * 2)
                          + ((lane >> 3) & 1) * 16;

    for (int t = 0; t < T; t++) {
        CP_WAIT(STG - 2);
        __syncthreads();
        const int tn = t + STG - 1;
        if (tn < T) {
            const int s = tn % STG;
            cp_async16(asb + s * ASZ, Ag + tn * BK);
            if (bld) cp_async16(wsb + s * WSZ, Wg + tn * BK);
        }
        CP_COMMIT();

        const int st = t % STG;
        uint32_t af[2][4];
        ldsm4(af[0], albase + st * ASZ);
        ldsm4(af[1], albase + st * ASZ + 16 * AROW * 2);

        uint32_t bq[2][4];
        ldsm4(bq[0], wbbase + st * WSZ);
        ldsm4(bq[1], wbbase + st * WSZ + 16 * (AROW * 2));

#pragma unroll
        for (int mt = 0; mt < 2; mt++) {
            mma_bf16(acc[mt][0], af[mt], &bq[0][0]);
            mma_bf16(acc[mt][1], af[mt], &bq[0][2]);
            mma_bf16(acc[mt][2], af[mt], &bq[1][0]);
            mma_bf16(acc[mt][3], af[mt], &bq[1][2]);
        }
    }

    __nv_bfloat16* outb = (__nv_bfloat16*)outp;
    float*         outf = (float*)outp;

#pragma unroll
    for (int mt = 0; mt < 2; mt++) {
        const int r0 = row0 + wm + mt * 16 + g;
        const int r1 = r0 + 8;

        if (EPI == 3) {
            const int d0 = src_index(r0);
            const int d1 = src_index(r1);
            float s0 = 0.0f, q0 = 0.0f, s1 = 0.0f, q1 = 0.0f;
#pragma unroll
            for (int nt = 0; nt < 4; nt++) {
                const int col = col0 + wn + nt * 8 + 2 * tin;
                const float2 bv = *(const float2*)&bias[col];
                float2 v0, v1;
                v0.x = acc[mt][nt][0] + bv.x;
                v0.y = acc[mt][nt][1] + bv.y;
                v1.x = acc[mt][nt][2] + bv.x;
                v1.y = acc[mt][nt][3] + bv.y;
                float2 e0 = *(const float2*)&res[(size_t)d0 * 192 + col];
                float2 e1 = *(const float2*)&res[(size_t)d1 * 192 + col];
                v0.x += e0.x; v0.y += e0.y;
                v1.x += e1.x; v1.y += e1.y;
                *(float2*)&outf[(size_t)d0 * 192 + col] = v0;
                *(float2*)&outf[(size_t)d1 * 192 + col] = v1;
                *(uint32_t*)&g_x2b[(size_t)d0 * 192 + col] = packbf(v0.x, v0.y);
                *(uint32_t*)&g_x2b[(size_t)d1 * 192 + col] = packbf(v1.x, v1.y);
                s0 += v0.x + v0.y; q0 += v0.x * v0.x + v0.y * v0.y;
                s1 += v1.x + v1.y; q1 += v1.x * v1.x + v1.y * v1.y;
            }
            s0 += __shfl_xor_sync(0xffffffffu, s0, 1);
            s0 += __shfl_xor_sync(0xffffffffu, s0, 2);
            q0 += __shfl_xor_sync(0xffffffffu, q0, 1);
            q0 += __shfl_xor_sync(0xffffffffu, q0, 2);
            s1 += __shfl_xor_sync(0xffffffffu, s1, 1);
            s1 += __shfl_xor_sync(0xffffffffu, s1, 2);
            q1 += __shfl_xor_sync(0xffffffffu, q1, 1);
            q1 += __shfl_xor_sync(0xffffffffu, q1, 2);
            if (tin == 0) {
                const int slot = blockIdx.x * 2 + (wid >> 2);
                g_pbuf[slot * NTOK + d0] = make_float2(s0, q0);
                g_pbuf[slot * NTOK + d1] = make_float2(s1, q1);
            }
        } else if (EPI == 4) {
            const float2 mr0 = g_mstat[r0];
            const float2 mr1 = g_mstat[r1];
            const float a0 = mr0.y, b0 = mr0.x * mr0.y;
            const float a1 = mr1.y, b1c = mr1.x * mr1.y;
#pragma unroll
            for (int nt = 0; nt < 4; nt++) {
                const int col = col0 + wn + nt * 8 + 2 * tin;
                const float2 bv = *(const float2*)&bias[col];
                const float2 stA = g_st1[col];
                const float2 stB = g_st1[col + 1];
                float v00 = gelu_exact(a0 * acc[mt][nt][0] - b0 * stA.x + stA.y + bv.x);
                float v01 = gelu_exact(a0 * acc[mt][nt][1] - b0 * stB.x + stB.y + bv.y);
                float v10 = gelu_exact(a1 * acc[mt][nt][2] - b1c * stA.x + stA.y + bv.x);
                float v11 = gelu_exact(a1 * acc[mt][nt][3] - b1c * stB.x + stB.y + bv.y);
                *(uint32_t*)&outb[(size_t)r0 * N + col] = packbf(v00, v01);
                *(uint32_t*)&outb[(size_t)r1 * N + col] = packbf(v10, v11);
            }
        } else {  // EPI 2
#pragma unroll
            for (int nt = 0; nt < 4; nt++) {
                const int col = col0 + wn + nt * 8 + 2 * tin;
                const float2 bv = *(const float2*)&bias[col];
                float2 v0, v1;
                v0.x = acc[mt][nt][0] + bv.x;
                v0.y = acc[mt][nt][1] + bv.y;
                v1.x = acc[mt][nt][2] + bv.x;
                v1.y = acc[mt][nt][3] + bv.y;
                float2 e0 = *(const float2*)&res[(size_t)r0 * N + col];
                float2 e1 = *(const float2*)&res[(size_t)r1 * N + col];
                v0.x += e0.x; v0.y += e0.y;
                v1.x += e1.x; v1.y += e1.y;
                *(float2*)&outf[(size_t)r0 * N + col] = v0;
                *(float2*)&outf[(size_t)r1 * N + col] = v1;
            }
        }
    }
}

// ---------------------------------------------------------------------------
// Launcher
// ---------------------------------------------------------------------------
extern "C" void kernel_launch(void* const* d_in, const int* in_sizes, int n_in,
                              void* d_out, int out_size) {
    const float* x     = (const float*)d_in[0];
    const float* ln1_g = (const float*)d_in[1];
    const float* ln1_b = (const float*)d_in[2];
    const float* ln2_g = (const float*)d_in[3];
    const float* ln2_b = (const float*)d_in[4];
    const float* w_qkv = (const float*)d_in[5];
    const float* b_qkv = (const float*)d_in[6];
    const float* w_out = (const float*)d_in[7];
    const float* b_out = (const float*)d_in[8];
    const float* w1    = (const float*)d_in[9];
    const float* b1    = (const float*)d_in[10];
    const float* w2    = (const float*)d_in[11];
    const float* b2    = (const float*)d_in[12];
    float* out = (float*)d_out;

    __nv_bfloat16 *aob, *x2b, *hid, *wo, *ww1, *ww2;
    float* x2;
    cudaGetSymbolAddress((void**)&aob, g_ao);
    cudaGetSymbolAddress((void**)&x2,  g_x2);
    cudaGetSymbolAddress((void**)&x2b, g_x2b);
    cudaGetSymbolAddress((void**)&hid, g_hid);
    cudaGetSymbolAddress((void**)&wo,  g_wout);
    cudaGetSymbolAddress((void**)&ww1, g_w1);
    cudaGetSymbolAddress((void**)&ww2, g_w2);

    cudaFuncSetAttribute(attn_fused, cudaFuncAttributeMaxDynamicSharedMemorySize, FUSED_SMEM);

    // 0) weight prep
    wcvt<<<864, 256>>>(w_qkv, w_out, w2);
    prep1<<<48, 256>>>(w1, ln2_g, ln2_b);
    // 1) fused LN1 + QKV GEMM + attention -> ao
    attn_fused<<<dim3(1024, 6), 256, FUSED_SMEM>>>(x, ln1_g, ln1_b, b_qkv, aob);
    // 2) proj + residual + scatter -> x2 fp32 + x2b bf16 + LN2 stat partials
    bgemm<3><<<dim3(3, NTOK / BM), 256>>>(aob, wo, b_out, x2, x, 192, 192);
    // 3) finalize LN2 stats
    finstats<<<NTOK / 256, 256>>>();
    // 4) fc1 (LN2 folded) + GELU -> hid
    bgemm<4><<<dim3(6, NTOK / BM), 256>>>(x2b, ww1, b1, hid, nullptr, 384, 192);
    // 5) fc2 + residual -> out
    bgemm<2><<<dim3(3, NTOK / BM), 256>>>(hid, ww2, b2, out, x2, 192, 384);
}

// round 9
// speedup vs baseline: 1.4227x; 1.4227x over previous
#include <cuda_runtime.h>
#include <cuda_bf16.h>
#include <math.h>
#include <stdint.h>

// ---------------------------------------------------------------------------
// Swin block: B=32, H=W=56, D=192, HEADS=6, DH=32, WS=7, SHIFT=3, no pad,
// no attention mask (per reference).
// R9: revert R8 LN1-fusion (regressed); R7 structure + BN=96 bgemm tiles
// (4m x 2n(48) warp layout) to cut fragment/global bytes per MMA.
// ---------------------------------------------------------------------------

#define NHW   3136
#define NTOK  100352
#define DIM   192
#define NWIN  2048

__device__ __nv_bfloat16 g_a1 [(size_t)NTOK * DIM];   // LN1 out (window order)
__device__ __nv_bfloat16 g_ao [(size_t)NTOK * DIM];   // attn out (window order)
__device__ float         g_x2 [(size_t)NTOK * DIM];   // x2 fp32 (plain order)
__device__ __nv_bfloat16 g_x2b[(size_t)NTOK * DIM];   // x2 bf16 (plain order)
__device__ __nv_bfloat16 g_hid[(size_t)NTOK * 384];   // fc1 GELU out
__device__ __nv_bfloat16 g_wqkv[576 * 192];
__device__ __nv_bfloat16 g_wout[192 * 192];
__device__ __nv_bfloat16 g_w1  [384 * 192];           // gamma2-folded
__device__ __nv_bfloat16 g_w2  [192 * 384];
__device__ float2        g_st1 [384];                 // (S_n, T_n) for fc1 affine
__device__ float2        g_pbuf[4 * NTOK];            // per-slot (sum, sumsq)
__device__ float2        g_mstat[NTOK];               // (mean, rstd) of x2
__device__ __align__(16) __nv_bfloat16 g_zbuf[16];    // zero page for A padding

__device__ __forceinline__ int src_index(int r) {
    int w = r / 49, p = r % 49;
    int b  = w >> 6;
    int wy = (w & 63) >> 3;
    int wx = w & 7;
    int py = p / 7, px = p % 7;
    int h2 = wy * 7 + py;
    int w2 = wx * 7 + px;
    int hs = h2 + 3; if (hs >= 56) hs -= 56;
    int ws = w2 + 3; if (ws >= 56) ws -= 56;
    return b * NHW + hs * 56 + ws;
}

// ---------------------------------------------------------------------------
// PTX helpers (sm_80+; safe on plain sm_100 ptxas target)
// ---------------------------------------------------------------------------
__device__ __forceinline__ uint32_t smem_u32(const void* p) {
    uint32_t a;
    asm("{ .reg .u64 t; cvta.to.shared.u64 t, %1; cvt.u32.u64 %0, t; }" : "=r"(a) : "l"(p));
    return a;
}
__device__ __forceinline__ void cp_async16(uint32_t dst, const void* src) {
    asm volatile("cp.async.ca.shared.global [%0], [%1], 16;" :: "r"(dst), "l"(src));
}
#define CP_COMMIT()  asm volatile("cp.async.commit_group;" ::: "memory")
#define CP_WAIT(n)   asm volatile("cp.async.wait_group %0;" :: "n"(n) : "memory")

__device__ __forceinline__ void ldsm4(uint32_t* r, uint32_t addr) {
    asm volatile("ldmatrix.sync.aligned.m8n8.x4.shared.b16 {%0,%1,%2,%3}, [%4];"
        : "=r"(r[0]), "=r"(r[1]), "=r"(r[2]), "=r"(r[3]) : "r"(addr));
}
__device__ __forceinline__ void ldsm2(uint32_t* r, uint32_t addr) {
    asm volatile("ldmatrix.sync.aligned.m8n8.x2.shared.b16 {%0,%1}, [%2];"
        : "=r"(r[0]), "=r"(r[1]) : "r"(addr));
}
__device__ __forceinline__ void ldsm4t(uint32_t* r, uint32_t addr) {
    asm volatile("ldmatrix.sync.aligned.m8n8.x4.trans.shared.b16 {%0,%1,%2,%3}, [%4];"
        : "=r"(r[0]), "=r"(r[1]), "=r"(r[2]), "=r"(r[3]) : "r"(addr));
}
__device__ __forceinline__ void mma_bf16(float* c, const uint32_t* a, const uint32_t* b) {
    asm volatile(
        "mma.sync.aligned.m16n8k16.row.col.f32.bf16.bf16.f32 "
        "{%0,%1,%2,%3}, {%4,%5,%6,%7}, {%8,%9}, {%0,%1,%2,%3};"
        : "+f"(c[0]), "+f"(c[1]), "+f"(c[2]), "+f"(c[3])
        : "r"(a[0]), "r"(a[1]), "r"(a[2]), "r"(a[3]), "r"(b[0]), "r"(b[1]));
}
__device__ __forceinline__ float gelu_exact(float v) {
    return 0.5f * v * (1.0f + erff(v * 0.7071067811865476f));
}
__device__ __forceinline__ uint32_t packbf(float a, float b) {
    __nv_bfloat162 t = __floats2bfloat162_rn(a, b);
    return *(uint32_t*)&t;
}

// ---------------------------------------------------------------------------
// Weight conversion fp32 -> bf16 (wqkv, wout, w2) + zero page
// ---------------------------------------------------------------------------
__global__ void wcvt(const float* __restrict__ wqkv, const float* __restrict__ wout,
                     const float* __restrict__ w2) {
    int i = blockIdx.x * 256 + threadIdx.x;
    if (i < 110592)       g_wqkv[i]          = __float2bfloat16(wqkv[i]);
    else if (i < 147456)  g_wout[i - 110592] = __float2bfloat16(wout[i - 110592]);
    else                  g_w2[i - 147456]   = __float2bfloat16(w2[i - 147456]);
    if (i < 16) g_zbuf[i] = __float2bfloat16(0.0f);
}

// Fold ln2 gamma into w1; compute per-n (S, T). One warp per n.
__global__ void prep1(const float* __restrict__ w1, const float* __restrict__ g2,
                      const float* __restrict__ b2) {
    int n = blockIdx.x * 8 + (threadIdx.x >> 5);
    int lane = threadIdx.x & 31;
    float S = 0.0f, T = 0.0f;
#pragma unroll
    for (int j = 0; j < 6; j++) {
        int k = lane + 32 * j;
        float w = w1[n * 192 + k];
        __nv_bfloat16 wb = __float2bfloat16(w * g2[k]);
        g_w1[n * 192 + k] = wb;
        S += __bfloat162float(wb);
        T += b2[k] * w;
    }
#pragma unroll
    for (int o = 16; o; o >>= 1) {
        S += __shfl_xor_sync(0xffffffffu, S, o);
        T += __shfl_xor_sync(0xffffffffu, T, o);
    }
    if (lane == 0) g_st1[n] = make_float2(S, T);
}

// Final LN2 stats: reduce the 4 proj-epilogue partial slots per token.
__global__ void finstats() {
    int i = blockIdx.x * 256 + threadIdx.x;
    float s = 0.0f, q = 0.0f;
#pragma unroll
    for (int k = 0; k < 4; k++) {
        float2 p = g_pbuf[k * NTOK + i];
        s += p.x; q += p.y;
    }
    float mean = s * (1.0f / 192.0f);
    float var  = q * (1.0f / 192.0f) - mean * mean;
    g_mstat[i] = make_float2(mean, rsqrtf(var + 1e-5f));
}

// ---------------------------------------------------------------------------
// LayerNorm 1: one warp per token, gather (shift+window partition), bf16 out.
// ---------------------------------------------------------------------------
__global__ void ln1_kernel(const float* __restrict__ x,
                           const float* __restrict__ gam,
                           const float* __restrict__ bet,
                           __nv_bfloat16* __restrict__ out) {
    int t    = blockIdx.x * 8 + (threadIdx.x >> 5);
    int lane = threadIdx.x & 31;
    const float* xr = x + (size_t)src_index(t) * DIM;

    float v[6];
#pragma unroll
    for (int i = 0; i < 6; i++) v[i] = xr[lane + 32 * i];

    float s = v[0] + v[1] + v[2] + v[3] + v[4] + v[5];
#pragma unroll
    for (int o = 16; o; o >>= 1) s += __shfl_xor_sync(0xffffffffu, s, o);
    float mean = s * (1.0f / 192.0f);

    float q = 0.0f;
#pragma unroll
    for (int i = 0; i < 6; i++) { float d = v[i] - mean; q += d * d; }
#pragma unroll
    for (int o = 16; o; o >>= 1) q += __shfl_xor_sync(0xffffffffu, q, o);
    float rstd = rsqrtf(q * (1.0f / 192.0f) + 1e-5f);

    __nv_bfloat16* orow = out + (size_t)t * DIM;
#pragma unroll
    for (int i = 0; i < 6; i++) {
        int c = lane + 32 * i;
        orow[c] = __float2bfloat16((v[i] - mean) * rstd * gam[c] + bet[c]);
    }
}

// ---------------------------------------------------------------------------
// Fused QKV-GEMM + window attention (round-7 version, unchanged).
// ---------------------------------------------------------------------------
#define FBK   16
#define FSTG  4
#define FAROW 24
#define FASZ  (128 * FAROW * 2)
#define FWSZ  (96 * FAROW * 2)
#define QSTR  104
#define OFF_WS (FSTG * FASZ)
#define OFF_QS (OFF_WS + FSTG * FWSZ)
#define FUSED_SMEM (OFF_QS + 128 * QSTR * 2)  // 69632 B

__global__ __launch_bounds__(256, 2)
void attn_fused(const __nv_bfloat16* __restrict__ a1,
                const float* __restrict__ bqkv,
                __nv_bfloat16* __restrict__ ao) {
    extern __shared__ char smem[];
    const int tid  = threadIdx.x;
    const int warp = tid >> 5;
    const int lane = tid & 31;
    const int g    = lane >> 2;
    const int tin  = lane & 3;
    const int l15  = lane & 15;
    const int lhi  = lane >> 4;
    const int p    = blockIdx.x;
    const int h    = blockIdx.y;
    const int R0   = p * 98;

    const int wm = (warp & 3) * 32;
    const int wn = (warp >> 2) * 48;

    const int arow = tid >> 1, achk = tid & 1;
    const bool areal = arow < 98;
    const __nv_bfloat16* Ag = areal ? (a1 + (size_t)(R0 + arow) * 192 + achk * 8)
                                    : (const __nv_bfloat16*)g_zbuf;
    const bool bld = tid < 192;
    int brow = (tid < 192) ? (tid >> 1) : 0;
    int bchk = tid & 1;
    const int bseg = brow >> 5;
    const __nv_bfloat16* Wg = g_wqkv + (size_t)(bseg * 192 + h * 32 + (brow & 31)) * 192 + bchk * 8;

    const uint32_t sb  = smem_u32(smem);
    const uint32_t asb = sb + (arow * FAROW + achk * 8) * 2;
    const uint32_t wsb = sb + OFF_WS + (brow * FAROW + bchk * 8) * 2;

#pragma unroll
    for (int s = 0; s < FSTG - 1; s++) {
        cp_async16(asb + s * FASZ, areal ? (Ag + s * FBK) : Ag);
        if (bld) cp_async16(wsb + s * FWSZ, Wg + s * FBK);
        CP_COMMIT();
    }

    float acc[2][6][4];
#pragma unroll
    for (int i = 0; i < 2; i++)
#pragma unroll
        for (int j = 0; j < 6; j++)
#pragma unroll
            for (int l = 0; l < 4; l++) acc[i][j][l] = 0.0f;

    const uint32_t albase = sb + ((wm + l15) * FAROW) * 2 + lhi * 16;
    const uint32_t wbbase = sb + OFF_WS
                          + (uint32_t)(wn + ((lane >> 4) & 1) * 8 + (lane & 7)) * (FAROW * 2)
                          + ((lane >> 3) & 1) * 16;

    for (int t = 0; t < 12; t++) {
        CP_WAIT(FSTG - 2);
        __syncthreads();
        const int tn = t + FSTG - 1;
        if (tn < 12) {
            const int s = tn % FSTG;
            cp_async16(asb + s * FASZ, areal ? (Ag + tn * FBK) : Ag);
            if (bld) cp_async16(wsb + s * FWSZ, Wg + tn * FBK);
        }
        CP_COMMIT();

        const int st = t % FSTG;
        uint32_t af[2][4];
        ldsm4(af[0], albase + st * FASZ);
        ldsm4(af[1], albase + st * FASZ + 16 * FAROW * 2);

        uint32_t bq[3][4];
#pragma unroll
        for (int pr = 0; pr < 3; pr++)
            ldsm4(bq[pr], wbbase + st * FWSZ + pr * 16 * (FAROW * 2));

#pragma unroll
        for (int mt = 0; mt < 2; mt++)
#pragma unroll
            for (int pr = 0; pr < 3; pr++) {
                mma_bf16(acc[mt][2 * pr + 0], af[mt], &bq[pr][0]);
                mma_bf16(acc[mt][2 * pr + 1], af[mt], &bq[pr][2]);
            }
    }

    __nv_bfloat16* qs = (__nv_bfloat16*)(smem + OFF_QS);
#pragma unroll
    for (int mt = 0; mt < 2; mt++) {
        const int r0 = wm + mt * 16 + g;
#pragma unroll
        for (int nt = 0; nt < 6; nt++) {
            const int nb  = wn + nt * 8;
            const int seg = nb >> 5;
            const int bcol = seg * 192 + h * 32 + (nb & 31) + 2 * tin;
            const float2 bv = *(const float2*)&bqkv[bcol];
            const int c = nb + 2 * tin;
            *(uint32_t*)&qs[r0 * QSTR + c]       = packbf(acc[mt][nt][0] + bv.x, acc[mt][nt][1] + bv.y);
            *(uint32_t*)&qs[(r0 + 8) * QSTR + c] = packbf(acc[mt][nt][2] + bv.x, acc[mt][nt][3] + bv.y);
        }
    }
    __syncthreads();

    // ---------------- Phase 2: attention ----------------
    const int wi = warp >> 2;
    const int mq = (warp & 3) * 16;
    const int rb = wi * 49 + mq;
    const uint32_t qsu = sb + OFF_QS;

    float a7[7][4];
#pragma unroll
    for (int nt = 0; nt < 7; nt++)
#pragma unroll
        for (int c = 0; c < 4; c++) a7[nt][c] = 0.0f;

    const uint32_t kbase = qsu
        + (uint32_t)(wi * 49 + ((lane >> 4) & 1) * 8 + (lane & 7)) * (QSTR * 2)
        + 64 + ((lane >> 3) & 1) * 16;

#pragma unroll
    for (int kc = 0; kc < 2; kc++) {
        uint32_t qa[4];
        ldsm4(qa, qsu + (uint32_t)(rb + l15) * (QSTR * 2) + kc * 32 + lhi * 16);
        uint32_t kq[3][4];
#pragma unroll
        for (int pr = 0; pr < 3; pr++)
            ldsm4(kq[pr], kbase + kc * 32 + pr * 16 * (QSTR * 2));
        uint32_t k6[2];
        ldsm2(k6, qsu + (uint32_t)(wi * 49 + 48 + (lane & 7)) * (QSTR * 2)
                   + 64 + kc * 32 + ((lane >> 3) & 1) * 16);
#pragma unroll
        for (int pr = 0; pr < 3; pr++) {
            mma_bf16(a7[2 * pr + 0], qa, &kq[pr][0]);
            mma_bf16(a7[2 * pr + 1], qa, &kq[pr][2]);
        }
        mma_bf16(a7[6], qa, k6);
    }

    const float scale = 0.17677669529663687f;
    float mx0 = -1e30f, mx1 = -1e30f;
#pragma unroll
    for (int nt = 0; nt < 7; nt++) {
        int c0 = nt * 8 + 2 * tin;
        float* a = a7[nt];
        a[0] = (c0     < 49) ? a[0] * scale : -1e30f;
        a[1] = (c0 + 1 < 49) ? a[1] * scale : -1e30f;
        a[2] = (c0     < 49) ? a[2] * scale : -1e30f;
        a[3] = (c0 + 1 < 49) ? a[3] * scale : -1e30f;
        mx0 = fmaxf(mx0, fmaxf(a[0], a[1]));
        mx1 = fmaxf(mx1, fmaxf(a[2], a[3]));
    }
    mx0 = fmaxf(mx0, __shfl_xor_sync(0xffffffffu, mx0, 1));
    mx0 = fmaxf(mx0, __shfl_xor_sync(0xffffffffu, mx0, 2));
    mx1 = fmaxf(mx1, __shfl_xor_sync(0xffffffffu, mx1, 1));
    mx1 = fmaxf(mx1, __shfl_xor_sync(0xffffffffu, mx1, 2));

    float s0 = 0.0f, s1 = 0.0f;
    uint32_t pk[8][2];
#pragma unroll
    for (int nt = 0; nt < 7; nt++) {
        float* a = a7[nt];
        a[0] = __expf(a[0] - mx0);
        a[1] = __expf(a[1] - mx0);
        a[2] = __expf(a[2] - mx1);
        a[3] = __expf(a[3] - mx1);
        s0 += a[0] + a[1];
        s1 += a[2] + a[3];
        pk[nt][0] = packbf(a[0], a[1]);
        pk[nt][1] = packbf(a[2], a[3]);
    }
    pk[7][0] = 0u; pk[7][1] = 0u;
    s0 += __shfl_xor_sync(0xffffffffu, s0, 1);
    s0 += __shfl_xor_sync(0xffffffffu, s0, 2);
    s1 += __shfl_xor_sync(0xffffffffu, s1, 1);
    s1 += __shfl_xor_sync(0xffffffffu, s1, 2);

    float pv[4][4];
#pragma unroll
    for (int nt = 0; nt < 4; nt++)
#pragma unroll
        for (int c = 0; c < 4; c++) pv[nt][c] = 0.0f;

    const uint32_t vbase = qsu + (uint32_t)(wi * 49 + l15) * (QSTR * 2) + 128 + lhi * 16;

#pragma unroll
    for (int kc = 0; kc < 4; kc++) {
        uint32_t pa[4] = { pk[2 * kc][0], pk[2 * kc][1], pk[2 * kc + 1][0], pk[2 * kc + 1][1] };
        uint32_t vq[2][4];
#pragma unroll
        for (int pr = 0; pr < 2; pr++)
            ldsm4t(vq[pr], vbase + kc * 16 * (QSTR * 2) + pr * 32);
#pragma unroll
        for (int pr = 0; pr < 2; pr++) {
            mma_bf16(pv[2 * pr + 0], pa, &vq[pr][0]);
            mma_bf16(pv[2 * pr + 1], pa, &vq[pr][2]);
        }
    }

    const float inv0 = 1.0f / s0;
    const float inv1 = 1.0f / s1;
    const int rr0 = mq + g;
    if (rr0 < 49) {
        __nv_bfloat16* ob = ao + (size_t)(R0 + wi * 49 + rr0) * 192 + h * 32;
#pragma unroll
        for (int nt = 0; nt < 4; nt++)
            *(uint32_t*)&ob[nt * 8 + 2 * tin] = packbf(pv[nt][0] * inv0, pv[nt][1] * inv0);
    }
    if (rr0 + 8 < 49) {
        __nv_bfloat16* ob = ao + (size_t)(R0 + wi * 49 + rr0 + 8) * 192 + h * 32;
#pragma unroll
        for (int nt = 0; nt < 4; nt++)
            *(uint32_t*)&ob[nt * 8 + 2 * tin] = packbf(pv[nt][2] * inv1, pv[nt][3] * inv1);
    }
}

// ---------------------------------------------------------------------------
// bf16 GEMM, BN=96 (4m x 2n(48) warp layout; 6 n-frags per warp). EPIs:
//   2: v += res[row]; fp32 store (fc2 -> out)
//   3: v += res[src(row)]; fp32 scatter store + bf16 copy + LN2 stat partials
//   4: LN2-affine (rstd*acc - mean*rstd*S + T + bias) then GELU, bf16 store
// ---------------------------------------------------------------------------
#define BM 128
#define BN 96
#define BK 16
#define STG 4
#define AROW 24

template <int EPI>
__global__ __launch_bounds__(256, 2)
void bgemm(const __nv_bfloat16* __restrict__ A, const __nv_bfloat16* __restrict__ W,
           const float* __restrict__ bias, void* __restrict__ outp,
           const float* __restrict__ res, int N, int K) {
    __shared__ __align__(16) __nv_bfloat16 As[STG][BM * AROW];
    __shared__ __align__(16) __nv_bfloat16 Ws[STG][BN * AROW];

    const int tid  = threadIdx.x;
    const int wid  = tid >> 5;
    const int lane = tid & 31;
    const int g    = lane >> 2;
    const int tin  = lane & 3;
    const int wm   = (wid & 3) * 32;
    const int wn   = (wid >> 2) * 48;
    const int row0 = blockIdx.y * BM;
    const int col0 = blockIdx.x * BN;

    const int arow = tid >> 1, achk = tid & 1;
    const bool bld = tid < 192;
    const int brow = bld ? (tid >> 1) : 0;
    const int bchk = tid & 1;

    const __nv_bfloat16* Ag = A + (size_t)(row0 + arow) * K + achk * 8;
    const __nv_bfloat16* Wg = W + (size_t)(col0 + brow) * K + bchk * 8;
    const uint32_t asb = smem_u32(As) + (arow * AROW + achk * 8) * 2;
    const uint32_t wsb = smem_u32(Ws) + (brow * AROW + bchk * 8) * 2;
    const uint32_t ASZ = BM * AROW * 2;
    const uint32_t WSZ = BN * AROW * 2;

    const int T = K / BK;
#pragma unroll
    for (int s = 0; s < STG - 1; s++) {
        cp_async16(asb + s * ASZ, Ag + s * BK);
        if (bld) cp_async16(wsb + s * WSZ, Wg + s * BK);
        CP_COMMIT();
    }

    float acc[2][6][4];
#pragma unroll
    for (int i = 0; i < 2; i++)
#pragma unroll
        for (int j = 0; j < 6; j++)
#pragma unroll
            for (int l = 0; l < 4; l++) acc[i][j][l] = 0.0f;

    const uint32_t albase = smem_u32(As) + ((wm + (lane & 15)) * AROW) * 2 + (lane >> 4) * 16;
    const uint32_t wbbase = smem_u32(Ws)
                          + (uint32_t)(wn + ((lane >> 4) & 1) * 8 + (lane & 7)) * (AROW * 2)
                          + ((lane >> 3) & 1) * 16;

    for (int t = 0; t < T; t++) {
        CP_WAIT(STG - 2);
        __syncthreads();
        const int tn = t + STG - 1;
        if (tn < T) {
            const int s = tn % STG;
            cp_async16(asb + s * ASZ, Ag + tn * BK);
            if (bld) cp_async16(wsb + s * WSZ, Wg + tn * BK);
        }
        CP_COMMIT();

        const int st = t % STG;
        uint32_t af[2][4];
        ldsm4(af[0], albase + st * ASZ);
        ldsm4(af[1], albase + st * ASZ + 16 * AROW * 2);

        uint32_t bq[3][4];
#pragma unroll
        for (int pr = 0; pr < 3; pr++)
            ldsm4(bq[pr], wbbase + st * WSZ + pr * 16 * (AROW * 2));

#pragma unroll
        for (int mt = 0; mt < 2; mt++)
#pragma unroll
            for (int pr = 0; pr < 3; pr++) {
                mma_bf16(acc[mt][2 * pr + 0], af[mt], &bq[pr][0]);
                mma_bf16(acc[mt][2 * pr + 1], af[mt], &bq[pr][2]);
            }
    }

    __nv_bfloat16* outb = (__nv_bfloat16*)outp;
    float*         outf = (float*)outp;

#pragma unroll
    for (int mt = 0; mt < 2; mt++) {
        const int r0 = row0 + wm + mt * 16 + g;
        const int r1 = r0 + 8;

        if (EPI == 3) {
            const int d0 = src_index(r0);
            const int d1 = src_index(r1);
            float s0 = 0.0f, q0 = 0.0f, s1 = 0.0f, q1 = 0.0f;
#pragma unroll
            for (int nt = 0; nt < 6; nt++) {
                const int col = col0 + wn + nt * 8 + 2 * tin;
                const float2 bv = *(const float2*)&bias[col];
                float2 v0, v1;
                v0.x = acc[mt][nt][0] + bv.x;
                v0.y = acc[mt][nt][1] + bv.y;
                v1.x = acc[mt][nt][2] + bv.x;
                v1.y = acc[mt][nt][3] + bv.y;
                float2 e0 = *(const float2*)&res[(size_t)d0 * 192 + col];
                float2 e1 = *(const float2*)&res[(size_t)d1 * 192 + col];
                v0.x += e0.x; v0.y += e0.y;
                v1.x += e1.x; v1.y += e1.y;
                *(float2*)&outf[(size_t)d0 * 192 + col] = v0;
                *(float2*)&outf[(size_t)d1 * 192 + col] = v1;
                *(uint32_t*)&g_x2b[(size_t)d0 * 192 + col] = packbf(v0.x, v0.y);
                *(uint32_t*)&g_x2b[(size_t)d1 * 192 + col] = packbf(v1.x, v1.y);
                s0 += v0.x + v0.y; q0 += v0.x * v0.x + v0.y * v0.y;
                s1 += v1.x + v1.y; q1 += v1.x * v1.x + v1.y * v1.y;
            }
            s0 += __shfl_xor_sync(0xffffffffu, s0, 1);
            s0 += __shfl_xor_sync(0xffffffffu, s0, 2);
            q0 += __shfl_xor_sync(0xffffffffu, q0, 1);
            q0 += __shfl_xor_sync(0xffffffffu, q0, 2);
            s1 += __shfl_xor_sync(0xffffffffu, s1, 1);
            s1 += __shfl_xor_sync(0xffffffffu, s1, 2);
            q1 += __shfl_xor_sync(0xffffffffu, q1, 1);
            q1 += __shfl_xor_sync(0xffffffffu, q1, 2);
            if (tin == 0) {
                const int slot = blockIdx.x * 2 + (wid >> 2);
                g_pbuf[slot * NTOK + d0] = make_float2(s0, q0);
                g_pbuf[slot * NTOK + d1] = make_float2(s1, q1);
            }
        } else if (EPI == 4) {
            const float2 mr0 = g_mstat[r0];
            const float2 mr1 = g_mstat[r1];
            const float a0 = mr0.y, b0 = mr0.x * mr0.y;
            const float a1 = mr1.y, b1c = mr1.x * mr1.y;
#pragma unroll
            for (int nt = 0; nt < 6; nt++) {
                const int col = col0 + wn + nt * 8 + 2 * tin;
                const float2 bv = *(const float2*)&bias[col];
                const float2 stA = g_st1[col];
                const float2 stB = g_st1[col + 1];
                float v00 = gelu_exact(a0 * acc[mt][nt][0] - b0 * stA.x + stA.y + bv.x);
                float v01 = gelu_exact(a0 * acc[mt][nt][1] - b0 * stB.x + stB.y + bv.y);
                float v10 = gelu_exact(a1 * acc[mt][nt][2] - b1c * stA.x + stA.y + bv.x);
                float v11 = gelu_exact(a1 * acc[mt][nt][3] - b1c * stB.x + stB.y + bv.y);
                *(uint32_t*)&outb[(size_t)r0 * N + col] = packbf(v00, v01);
                *(uint32_t*)&outb[(size_t)r1 * N + col] = packbf(v10, v11);
            }
        } else {  // EPI 2
#pragma unroll
            for (int nt = 0; nt < 6; nt++) {
                const int col = col0 + wn + nt * 8 + 2 * tin;
                const float2 bv = *(const float2*)&bias[col];
                float2 v0, v1;
                v0.x = acc[mt][nt][0] + bv.x;
                v0.y = acc[mt][nt][1] + bv.y;
                v1.x = acc[mt][nt][2] + bv.x;
                v1.y = acc[mt][nt][3] + bv.y;
                float2 e0 = *(const float2*)&res[(size_t)r0 * N + col];
                float2 e1 = *(const float2*)&res[(size_t)r1 * N + col];
                v0.x += e0.x; v0.y += e0.y;
                v1.x += e1.x; v1.y += e1.y;
                *(float2*)&outf[(size_t)r0 * N + col] = v0;
                *(float2*)&outf[(size_t)r1 * N + col] = v1;
            }
        }
    }
}

// ---------------------------------------------------------------------------
// Launcher
// ---------------------------------------------------------------------------
extern "C" void kernel_launch(void* const* d_in, const int* in_sizes, int n_in,
                              void* d_out, int out_size) {
    const float* x     = (const float*)d_in[0];
    const float* ln1_g = (const float*)d_in[1];
    const float* ln1_b = (const float*)d_in[2];
    const float* ln2_g = (const float*)d_in[3];
    const float* ln2_b = (const float*)d_in[4];
    const float* w_qkv = (const float*)d_in[5];
    const float* b_qkv = (const float*)d_in[6];
    const float* w_out = (const float*)d_in[7];
    const float* b_out = (const float*)d_in[8];
    const float* w1    = (const float*)d_in[9];
    const float* b1    = (const float*)d_in[10];
    const float* w2    = (const float*)d_in[11];
    const float* b2    = (const float*)d_in[12];
    float* out = (float*)d_out;

    __nv_bfloat16 *a1, *aob, *x2b, *hid, *wo, *ww1, *ww2;
    float* x2;
    cudaGetSymbolAddress((void**)&a1,  g_a1);
    cudaGetSymbolAddress((void**)&aob, g_ao);
    cudaGetSymbolAddress((void**)&x2,  g_x2);
    cudaGetSymbolAddress((void**)&x2b, g_x2b);
    cudaGetSymbolAddress((void**)&hid, g_hid);
    cudaGetSymbolAddress((void**)&wo,  g_wout);
    cudaGetSymbolAddress((void**)&ww1, g_w1);
    cudaGetSymbolAddress((void**)&ww2, g_w2);

    cudaFuncSetAttribute(attn_fused, cudaFuncAttributeMaxDynamicSharedMemorySize, FUSED_SMEM);

    // 0) weight prep
    wcvt<<<864, 256>>>(w_qkv, w_out, w2);
    prep1<<<48, 256>>>(w1, ln2_g, ln2_b);
    // 1) LN1 + shift + window partition -> a1 (bf16, window order)
    ln1_kernel<<<NTOK / 8, 256>>>(x, ln1_g, ln1_b, a1);
    // 2) fused QKV GEMM + attention -> ao (qkv stays in SMEM)
    attn_fused<<<dim3(1024, 6), 256, FUSED_SMEM>>>(a1, b_qkv, aob);
    // 3) proj + residual + scatter -> x2 fp32 + x2b bf16 + LN2 stat partials
    bgemm<3><<<dim3(2, NTOK / BM), 256>>>(aob, wo, b_out, x2, x, 192, 192);
    // 4) finalize LN2 stats
    finstats<<<NTOK / 256, 256>>>();
    // 5) fc1 (LN2 folded) + GELU -> hid
    bgemm<4><<<dim3(4, NTOK / BM), 256>>>(x2b, ww1, b1, hid, nullptr, 384, 192);
    // 6) fc2 + residual -> out
    bgemm<2><<<dim3(2, NTOK / BM), 256>>>(hid, ww2, b2, out, x2, 192, 384);
}